// round 1
// baseline (speedup 1.0000x reference)
#include <cuda_runtime.h>
#include <math.h>

#define N_BOX 400
#define C_CLS 151
#define D_X   4096
#define E_EMB 200
#define H_DIM 512
#define P_POS 128
#define K_REP  (D_X + E_EMB + P_POS)   /* 4424 */
#define K_REP2 (D_X + P_POS)           /* 4224 */
#define FNEG_INF (-3.402823466e38f)

// ---------------- scratch (no allocations allowed) ----------------
__device__ float g_rep [N_BOX * K_REP];
__device__ float g_rep2[N_BOX * K_REP2];
__device__ float g_h1  [N_BOX * H_DIM];
__device__ float g_fcb [N_BOX * H_DIM];
__device__ float g_tab [C_CLS * H_DIM];
__device__ float g_scores[N_BOX * C_CLS];
__device__ int   g_labels[N_BOX];

// ---------------- helpers ----------------
__device__ __forceinline__ float warp_max(float v) {
    #pragma unroll
    for (int o = 16; o; o >>= 1) v = fmaxf(v, __shfl_xor_sync(0xffffffffu, v, o));
    return v;
}
__device__ __forceinline__ float warp_sum(float v) {
    #pragma unroll
    for (int o = 16; o; o >>= 1) v += __shfl_xor_sync(0xffffffffu, v, o);
    return v;
}

// ---------------- prep: softmax(logits)@obj_embed_w, pos MLP, build rep/rep2 ----------------
__global__ __launch_bounds__(256) void prep_kernel(
    const float* __restrict__ x, const float* __restrict__ logits,
    const float* __restrict__ pos, const float* __restrict__ obj_embed_w,
    const float* __restrict__ w_pos1, const float* __restrict__ b_pos1,
    const float* __restrict__ bn_g, const float* __restrict__ bn_b,
    const float* __restrict__ bn_m, const float* __restrict__ bn_v,
    const float* __restrict__ w_pos2, const float* __restrict__ b_pos2)
{
    int row = blockIdx.x, tid = threadIdx.x;
    __shared__ float sp[C_CLS];
    __shared__ float sh[32];
    __shared__ float sred[8];

    float lv = (tid < C_CLS) ? logits[row * C_CLS + tid] : FNEG_INF;
    float m = warp_max(lv);
    if ((tid & 31) == 0) sred[tid >> 5] = m;
    __syncthreads();
    float bm = sred[0];
    #pragma unroll
    for (int i = 1; i < 8; i++) bm = fmaxf(bm, sred[i]);
    float e = (tid < C_CLS) ? expf(lv - bm) : 0.f;
    float s = warp_sum(e);
    __syncthreads();
    if ((tid & 31) == 0) sred[tid >> 5] = s;
    __syncthreads();
    float bs = 0.f;
    #pragma unroll
    for (int i = 0; i < 8; i++) bs += sred[i];
    if (tid < C_CLS) sp[tid] = e / bs;

    if (tid < 32) {
        float acc = b_pos1[tid];
        #pragma unroll
        for (int k = 0; k < 9; k++) acc += pos[row * 9 + k] * w_pos1[k * 32 + tid];
        acc = (acc - bn_m[tid]) / sqrtf(bn_v[tid] + 1e-5f) * bn_g[tid] + bn_b[tid];
        sh[tid] = acc;
    }
    __syncthreads();

    if (tid < E_EMB) {
        float acc = 0.f;
        for (int k = 0; k < C_CLS; k++) acc += sp[k] * obj_embed_w[k * E_EMB + tid];
        g_rep[row * K_REP + D_X + tid] = acc;
    }
    if (tid < P_POS) {
        float acc = b_pos2[tid];
        #pragma unroll
        for (int k = 0; k < 32; k++) acc += sh[k] * w_pos2[k * P_POS + tid];
        acc = fmaxf(acc, 0.f);
        g_rep [row * K_REP  + D_X + E_EMB + tid] = acc;
        g_rep2[row * K_REP2 + D_X + tid] = acc;
    }
    const float4* xs = (const float4*)(x + (size_t)row * D_X);
    float4* r1 = (float4*)(g_rep  + (size_t)row * K_REP);
    float4* r2 = (float4*)(g_rep2 + (size_t)row * K_REP2);
    for (int i = tid; i < D_X / 4; i += 256) { float4 v = xs[i]; r1[i] = v; r2[i] = v; }
}

// ---------------- generic fp32 SGEMM: C = A(MxK)B(KxN) + bias, optional relu ----------------
// BM=16, BN=128, BK=16, 128 threads, thread tile 4x4
#define BM 16
#define BN 128
#define BK 16
__global__ __launch_bounds__(128) void sgemm_kernel(
    const float* __restrict__ A, int lda,
    const float* __restrict__ B, int ldb,
    float* __restrict__ C, int ldc,
    int M, int N, int K,
    const float* __restrict__ bias, int relu)
{
    __shared__ float As[BK][BM + 1];
    __shared__ float Bs[BK][BN];
    int tid = threadIdx.x;
    int tx = tid & 31;     // 32 col groups of 4
    int ty = tid >> 5;     // 4 row groups of 4
    int row0 = blockIdx.y * BM;
    int col0 = blockIdx.x * BN;
    float acc[4][4];
    #pragma unroll
    for (int i = 0; i < 4; i++)
        #pragma unroll
        for (int j = 0; j < 4; j++) acc[i][j] = 0.f;

    bool bvec = ((ldb & 3) == 0);

    for (int k0 = 0; k0 < K; k0 += BK) {
        // A tile: 16x16 = 256 floats / 128 thr = 2 each (stored transposed)
        #pragma unroll
        for (int i = 0; i < 2; i++) {
            int l = tid * 2 + i;
            int m = l >> 4;
            int k = l & 15;
            int gr = row0 + m, gk = k0 + k;
            As[k][m] = (gr < M && gk < K) ? A[(size_t)gr * lda + gk] : 0.f;
        }
        // B tile: 16x128 = 2048 floats = 512 float4 / 128 thr = 4 each
        #pragma unroll
        for (int i = 0; i < 4; i++) {
            int f = tid + i * 128;
            int k = f >> 5;
            int n = (f & 31) << 2;
            int gk = k0 + k, gn = col0 + n;
            float4 v = make_float4(0.f, 0.f, 0.f, 0.f);
            if (gk < K) {
                if (bvec && gn + 3 < N) {
                    v = *(const float4*)(B + (size_t)gk * ldb + gn);
                } else {
                    float t0 = (gn + 0 < N) ? B[(size_t)gk * ldb + gn + 0] : 0.f;
                    float t1 = (gn + 1 < N) ? B[(size_t)gk * ldb + gn + 1] : 0.f;
                    float t2 = (gn + 2 < N) ? B[(size_t)gk * ldb + gn + 2] : 0.f;
                    float t3 = (gn + 3 < N) ? B[(size_t)gk * ldb + gn + 3] : 0.f;
                    v = make_float4(t0, t1, t2, t3);
                }
            }
            *(float4*)&Bs[k][n] = v;
        }
        __syncthreads();
        #pragma unroll
        for (int k = 0; k < BK; k++) {
            float a0 = As[k][ty * 4 + 0];
            float a1 = As[k][ty * 4 + 1];
            float a2 = As[k][ty * 4 + 2];
            float a3 = As[k][ty * 4 + 3];
            float4 bv = *(float4*)&Bs[k][tx * 4];
            acc[0][0] += a0 * bv.x; acc[0][1] += a0 * bv.y; acc[0][2] += a0 * bv.z; acc[0][3] += a0 * bv.w;
            acc[1][0] += a1 * bv.x; acc[1][1] += a1 * bv.y; acc[1][2] += a1 * bv.z; acc[1][3] += a1 * bv.w;
            acc[2][0] += a2 * bv.x; acc[2][1] += a2 * bv.y; acc[2][2] += a2 * bv.z; acc[2][3] += a2 * bv.w;
            acc[3][0] += a3 * bv.x; acc[3][1] += a3 * bv.y; acc[3][2] += a3 * bv.z; acc[3][3] += a3 * bv.w;
        }
        __syncthreads();
    }
    #pragma unroll
    for (int i = 0; i < 4; i++) {
        int gr = row0 + ty * 4 + i;
        if (gr >= M) continue;
        #pragma unroll
        for (int j = 0; j < 4; j++) {
            int gn = col0 + tx * 4 + j;
            if (gn >= N) continue;
            float v = acc[i][j];
            if (bias) v += bias[gn];
            if (relu) v = fmaxf(v, 0.f);
            C[(size_t)gr * ldc + gn] = v;
        }
    }
}

// ---------------- row softmax of obj_dists -> g_scores (col 0 = -1) ----------------
__global__ __launch_bounds__(256) void scores_kernel(const float* __restrict__ obj_dists)
{
    int row = blockIdx.x, tid = threadIdx.x;
    __shared__ float sred[8];
    float lv = (tid < C_CLS) ? obj_dists[row * C_CLS + tid] : FNEG_INF;
    float m = warp_max(lv);
    if ((tid & 31) == 0) sred[tid >> 5] = m;
    __syncthreads();
    float bm = sred[0];
    #pragma unroll
    for (int i = 1; i < 8; i++) bm = fmaxf(bm, sred[i]);
    float e = (tid < C_CLS) ? expf(lv - bm) : 0.f;
    float s = warp_sum(e);
    __syncthreads();
    if ((tid & 31) == 0) sred[tid >> 5] = s;
    __syncthreads();
    float bs = 0.f;
    #pragma unroll
    for (int i = 0; i < 8; i++) bs += sred[i];
    if (tid < C_CLS) g_scores[row * C_CLS + tid] = (tid == 0) ? -1.f : e / bs;
}

// ---------------- greedy NMS labeling (single block, sequential 400 iters) ----------------
__global__ __launch_bounds__(512, 1) void greedy_kernel(const float* __restrict__ boxes)
{
    const int NT = 512;
    int tid = threadIdx.x;
    __shared__ float s_rowmax[N_BOX];
    __shared__ int   s_rowarg[N_BOX];
    __shared__ float s_rv[16];
    __shared__ int   s_ri[16];
    __shared__ int   s_box, s_cls;
    __shared__ float s_b0, s_b1, s_b2, s_b3, s_barea;
    __shared__ int   s_q[N_BOX];
    __shared__ int   s_qn;

    // init row caches (scores exact: col0=-1, rest softmax>0)
    for (int r = tid; r < N_BOX; r += NT) {
        float best = -2.f; int bi = 0;
        const float* sr = g_scores + r * C_CLS;
        for (int c = 0; c < C_CLS; c++) {
            float v = sr[c];
            if (v > best) { best = v; bi = c; }
        }
        s_rowmax[r] = best; s_rowarg[r] = bi;
        g_labels[r] = 0;
    }
    __syncthreads();

    for (int it = 0; it < N_BOX; it++) {
        // ---- Phase A: argmax over row maxima (ties -> smallest row) ----
        float v = (tid < N_BOX) ? s_rowmax[tid] : FNEG_INF;
        int idx = tid;
        #pragma unroll
        for (int o = 16; o; o >>= 1) {
            float ov = __shfl_xor_sync(0xffffffffu, v, o);
            int   oi = __shfl_xor_sync(0xffffffffu, idx, o);
            if (ov > v || (ov == v && oi < idx)) { v = ov; idx = oi; }
        }
        if ((tid & 31) == 0) { s_rv[tid >> 5] = v; s_ri[tid >> 5] = idx; }
        __syncthreads();
        if (tid < 32) {
            float v2 = (tid < 16) ? s_rv[tid] : FNEG_INF;
            int   i2 = (tid < 16) ? s_ri[tid] : 0x7fffffff;
            #pragma unroll
            for (int o = 8; o; o >>= 1) {
                float ov = __shfl_xor_sync(0xffffffffu, v2, o);
                int   oi = __shfl_xor_sync(0xffffffffu, i2, o);
                if (ov > v2 || (ov == v2 && oi < i2)) { v2 = ov; i2 = oi; }
            }
            if (tid == 0) {
                int box = i2;
                int cls = s_rowarg[box];
                s_box = box; s_cls = cls;
                g_labels[box] = cls;
                float4 bb = *(const float4*)(boxes + ((size_t)box * C_CLS + cls) * 4);
                s_b0 = bb.x; s_b1 = bb.y; s_b2 = bb.z; s_b3 = bb.w;
                s_barea = (bb.z - bb.x + 1.f) * (bb.w - bb.y + 1.f);
                s_qn = 0;
            }
        }
        __syncthreads();
        int box = s_box, cls = s_cls;

        // ---- Phase B: mask overlapping column entries + retire selected row ----
        if (tid < N_BOX) {
            int r = tid;
            if (r == box) {
                s_rowmax[r] = -1.f; s_rowarg[r] = 0;
            } else {
                float4 bb = *(const float4*)(boxes + ((size_t)r * C_CLS + cls) * 4);
                float x1 = fmaxf(bb.x, s_b0);
                float y1 = fmaxf(bb.y, s_b1);
                float x2 = fminf(bb.z, s_b2);
                float y2 = fminf(bb.w, s_b3);
                float iw = fmaxf(x2 - x1 + 1.f, 0.f);
                float ih = fmaxf(y2 - y1 + 1.f, 0.f);
                float inter = iw * ih;
                float area = (bb.z - bb.x + 1.f) * (bb.w - bb.y + 1.f);
                float uni = area + s_barea - inter;
                if (inter / uni >= 0.5f) {
                    g_scores[r * C_CLS + cls] = 0.f;
                    int   ac = s_rowarg[r];
                    float mx = s_rowmax[r];
                    if (ac == cls) {
                        int qi = atomicAdd(&s_qn, 1);
                        s_q[qi] = r;
                    } else if (0.f > mx) {
                        s_rowmax[r] = 0.f; s_rowarg[r] = cls;
                    } else if (0.f == mx && cls < ac) {
                        s_rowarg[r] = cls;
                    }
                }
            }
        } else {
            int c = tid - N_BOX;               // 0..111
            if (c < C_CLS) g_scores[box * C_CLS + c] = -1.f;
            c += (NT - N_BOX);                 // +112 -> 112..223
            if (c < C_CLS) g_scores[box * C_CLS + c] = -1.f;
        }
        __syncthreads();

        // ---- Phase C: full rescan for rows whose cached max was invalidated ----
        int nq = s_qn;
        int wid = tid >> 5, lane = tid & 31;
        for (int qi = wid; qi < nq; qi += 16) {
            int r = s_q[qi];
            float best = -2.f; int bi = 0x7fffffff;
            const float* sr = g_scores + r * C_CLS;
            for (int c = lane; c < C_CLS; c += 32) {
                float vv = sr[c];
                if (vv > best || (vv == best && c < bi)) { best = vv; bi = c; }
            }
            #pragma unroll
            for (int o = 16; o; o >>= 1) {
                float ov = __shfl_xor_sync(0xffffffffu, best, o);
                int   oi = __shfl_xor_sync(0xffffffffu, bi, o);
                if (ov > best || (ov == best && oi < bi)) { best = ov; bi = oi; }
            }
            if (lane == 0) { s_rowmax[r] = best; s_rowarg[r] = bi; }
        }
        __syncthreads();
    }
}

// ---------------- final: edge_ctx = relu(fc_base + table[label]); write preds ----------------
__global__ __launch_bounds__(128) void edge_kernel(float* __restrict__ out)
{
    int row = blockIdx.x, tid = threadIdx.x;
    int lab = g_labels[row];
    if (tid == 0) out[N_BOX * C_CLS + row] = (float)lab;
    const float* fb = g_fcb + (size_t)row * H_DIM;
    const float* tb = g_tab + (size_t)lab * H_DIM;
    float* o = out + N_BOX * C_CLS + N_BOX + (size_t)row * H_DIM;
    for (int c = tid; c < H_DIM; c += 128) o[c] = fmaxf(fb[c] + tb[c], 0.f);
}

// ---------------- launch ----------------
extern "C" void kernel_launch(void* const* d_in, const int* in_sizes, int n_in,
                              void* d_out, int out_size)
{
    const float* x        = (const float*)d_in[0];
    const float* logits   = (const float*)d_in[1];
    const float* pos      = (const float*)d_in[2];
    const float* boxes    = (const float*)d_in[3];
    const float* objw     = (const float*)d_in[4];
    const float* objw2    = (const float*)d_in[5];
    const float* w_pos1   = (const float*)d_in[6];
    const float* b_pos1   = (const float*)d_in[7];
    const float* bn_g     = (const float*)d_in[8];
    const float* bn_b     = (const float*)d_in[9];
    const float* bn_m     = (const float*)d_in[10];
    const float* bn_v     = (const float*)d_in[11];
    const float* w_pos2   = (const float*)d_in[12];
    const float* b_pos2   = (const float*)d_in[13];
    const float* w_lin    = (const float*)d_in[14];
    const float* b_lin    = (const float*)d_in[15];
    const float* w_out    = (const float*)d_in[16];
    const float* b_out    = (const float*)d_in[17];
    const float* w_fc     = (const float*)d_in[18];
    const float* b_fc     = (const float*)d_in[19];
    float* out = (float*)d_out;

    float *rep, *rep2, *h1, *fcb, *tab;
    cudaGetSymbolAddress((void**)&rep,  g_rep);
    cudaGetSymbolAddress((void**)&rep2, g_rep2);
    cudaGetSymbolAddress((void**)&h1,   g_h1);
    cudaGetSymbolAddress((void**)&fcb,  g_fcb);
    cudaGetSymbolAddress((void**)&tab,  g_tab);

    // 1) feature prep
    prep_kernel<<<N_BOX, 256>>>(x, logits, pos, objw, w_pos1, b_pos1,
                                bn_g, bn_b, bn_m, bn_v, w_pos2, b_pos2);
    // 2) h1 = rep @ w_lin + b_lin
    sgemm_kernel<<<dim3(H_DIM / BN, (N_BOX + BM - 1) / BM), 128>>>(
        rep, K_REP, w_lin, H_DIM, h1, H_DIM, N_BOX, H_DIM, K_REP, b_lin, 0);
    // 3) obj_dists = h1 @ w_out + b_out  -> out[0 : 400*151]
    sgemm_kernel<<<dim3((C_CLS + BN - 1) / BN, (N_BOX + BM - 1) / BM), 128>>>(
        h1, H_DIM, w_out, C_CLS, out, C_CLS, N_BOX, C_CLS, H_DIM, b_out, 0);
    // 4) scores = softmax(obj_dists), col0 = -1
    scores_kernel<<<N_BOX, 256>>>(out);
    // 5) fc_base = [x|pos_embed] @ w_fc[0:4224] + b_fc   (independent of NMS)
    sgemm_kernel<<<dim3(H_DIM / BN, (N_BOX + BM - 1) / BM), 128>>>(
        rep2, K_REP2, w_fc, H_DIM, fcb, H_DIM, N_BOX, H_DIM, K_REP2, b_fc, 0);
    // 6) table = obj_embed2_w @ w_fc[4224:4424]
    sgemm_kernel<<<dim3(H_DIM / BN, (C_CLS + BM - 1) / BM), 128>>>(
        objw2, E_EMB, w_fc + (size_t)K_REP2 * H_DIM, H_DIM, tab, H_DIM,
        C_CLS, H_DIM, E_EMB, (const float*)0, 0);
    // 7) sequential greedy NMS labeling
    greedy_kernel<<<1, 512>>>(boxes);
    // 8) edge_ctx = relu(fc_base + table[label]); preds as float
    edge_kernel<<<N_BOX, 128>>>(out);
}

// round 2
// speedup vs baseline: 2.5282x; 2.5282x over previous
#include <cuda_runtime.h>
#include <math.h>

#define N_BOX 400
#define C_CLS 151
#define D_X   4096
#define E_EMB 200
#define H_DIM 512
#define P_POS 128
#define K_REP  (D_X + E_EMB + P_POS)   /* 4424 */
#define K_REP2 (D_X + P_POS)           /* 4224 */
#define TAIL_W (E_EMB + P_POS)         /* 328  */
#define FNEG_INF (-3.402823466e38f)
#define NSPLIT 4
#define KSPLIT (K_REP / NSPLIT)        /* 1106 */

// ---------------- scratch (no allocations allowed) ----------------
__device__ float g_tail[N_BOX * TAIL_W];          // [obj_embed | pos_embed]
__device__ float g_part[NSPLIT * N_BOX * H_DIM];  // split-K partials
__device__ float g_h1  [N_BOX * H_DIM];
__device__ float g_fcb [N_BOX * H_DIM];
__device__ float g_tab [C_CLS * H_DIM];
__device__ float g_scores[N_BOX * C_CLS];
__device__ float g_boxT[C_CLS * N_BOX * 4];       // boxesT[cls][r] float4
__device__ int   g_labels[N_BOX];

// ---------------- helpers ----------------
__device__ __forceinline__ float warp_max(float v) {
    #pragma unroll
    for (int o = 16; o; o >>= 1) v = fmaxf(v, __shfl_xor_sync(0xffffffffu, v, o));
    return v;
}
__device__ __forceinline__ float warp_sum(float v) {
    #pragma unroll
    for (int o = 16; o; o >>= 1) v += __shfl_xor_sync(0xffffffffu, v, o);
    return v;
}

// ---------------- boxes transpose: boxT[c][r] = boxes[r][c] ----------------
__global__ __launch_bounds__(160) void transpose_boxes(const float* __restrict__ boxes)
{
    int r = blockIdx.x, c = threadIdx.x;
    if (c < C_CLS) {
        float4 v = ((const float4*)boxes)[(size_t)r * C_CLS + c];
        ((float4*)g_boxT)[(size_t)c * N_BOX + r] = v;
    }
}

// ---------------- prep: softmax(logits)@obj_embed_w, pos MLP -> g_tail ----------------
__global__ __launch_bounds__(256) void prep_kernel(
    const float* __restrict__ logits,
    const float* __restrict__ pos, const float* __restrict__ obj_embed_w,
    const float* __restrict__ w_pos1, const float* __restrict__ b_pos1,
    const float* __restrict__ bn_g, const float* __restrict__ bn_b,
    const float* __restrict__ bn_m, const float* __restrict__ bn_v,
    const float* __restrict__ w_pos2, const float* __restrict__ b_pos2)
{
    int row = blockIdx.x, tid = threadIdx.x;
    __shared__ float sp[C_CLS];
    __shared__ float sh[32];
    __shared__ float sred[8];

    float lv = (tid < C_CLS) ? logits[row * C_CLS + tid] : FNEG_INF;
    float m = warp_max(lv);
    if ((tid & 31) == 0) sred[tid >> 5] = m;
    __syncthreads();
    float bm = sred[0];
    #pragma unroll
    for (int i = 1; i < 8; i++) bm = fmaxf(bm, sred[i]);
    float e = (tid < C_CLS) ? expf(lv - bm) : 0.f;
    float s = warp_sum(e);
    __syncthreads();
    if ((tid & 31) == 0) sred[tid >> 5] = s;
    __syncthreads();
    float bs = 0.f;
    #pragma unroll
    for (int i = 0; i < 8; i++) bs += sred[i];
    if (tid < C_CLS) sp[tid] = e / bs;

    if (tid < 32) {
        float acc = b_pos1[tid];
        #pragma unroll
        for (int k = 0; k < 9; k++) acc += pos[row * 9 + k] * w_pos1[k * 32 + tid];
        acc = (acc - bn_m[tid]) / sqrtf(bn_v[tid] + 1e-5f) * bn_g[tid] + bn_b[tid];
        sh[tid] = acc;
    }
    __syncthreads();

    if (tid < E_EMB) {
        float acc = 0.f;
        for (int k = 0; k < C_CLS; k++) acc += sp[k] * obj_embed_w[k * E_EMB + tid];
        g_tail[row * TAIL_W + tid] = acc;
    }
    if (tid < P_POS) {
        float acc = b_pos2[tid];
        #pragma unroll
        for (int k = 0; k < 32; k++) acc += sh[k] * w_pos2[k * P_POS + tid];
        g_tail[row * TAIL_W + E_EMB + tid] = fmaxf(acc, 0.f);
    }
}

// ---------------- h1 split-K GEMM: part[s] = rep[:,kbeg:kend] @ w_lin[kbeg:kend,:] ----------------
// BM=16, BN=128, BK=16, 128 threads, 4x4 per thread. grid (4, 25, NSPLIT). M,N exact.
__global__ __launch_bounds__(128) void h1_splitk_kernel(
    const float* __restrict__ x, const float* __restrict__ wlin)
{
    __shared__ float As[16][17];
    __shared__ float Bs[16][128];
    int tid = threadIdx.x;
    int tx = tid & 31, ty = tid >> 5;
    int row0 = blockIdx.y * 16;
    int col0 = blockIdx.x * 128;
    int s    = blockIdx.z;
    int kbeg = s * KSPLIT, kend = kbeg + KSPLIT;

    float acc[4][4];
    #pragma unroll
    for (int i = 0; i < 4; i++)
        #pragma unroll
        for (int j = 0; j < 4; j++) acc[i][j] = 0.f;

    for (int k0 = kbeg; k0 < kend; k0 += 16) {
        #pragma unroll
        for (int i = 0; i < 2; i++) {
            int l = tid * 2 + i;
            int m = l >> 4, k = l & 15;
            int gr = row0 + m, gk = k0 + k;
            float v = 0.f;
            if (gk < kend)
                v = (gk < D_X) ? x[(size_t)gr * D_X + gk]
                               : g_tail[gr * TAIL_W + (gk - D_X)];
            As[k][m] = v;
        }
        #pragma unroll
        for (int i = 0; i < 4; i++) {
            int f = tid + i * 128;
            int k = f >> 5, n = (f & 31) << 2;
            int gk = k0 + k;
            float4 v = make_float4(0.f, 0.f, 0.f, 0.f);
            if (gk < kend) v = *(const float4*)(wlin + (size_t)gk * H_DIM + col0 + n);
            *(float4*)&Bs[k][n] = v;
        }
        __syncthreads();
        #pragma unroll
        for (int k = 0; k < 16; k++) {
            float a0 = As[k][ty * 4 + 0];
            float a1 = As[k][ty * 4 + 1];
            float a2 = As[k][ty * 4 + 2];
            float a3 = As[k][ty * 4 + 3];
            float4 bv = *(float4*)&Bs[k][tx * 4];
            acc[0][0] += a0 * bv.x; acc[0][1] += a0 * bv.y; acc[0][2] += a0 * bv.z; acc[0][3] += a0 * bv.w;
            acc[1][0] += a1 * bv.x; acc[1][1] += a1 * bv.y; acc[1][2] += a1 * bv.z; acc[1][3] += a1 * bv.w;
            acc[2][0] += a2 * bv.x; acc[2][1] += a2 * bv.y; acc[2][2] += a2 * bv.z; acc[2][3] += a2 * bv.w;
            acc[3][0] += a3 * bv.x; acc[3][1] += a3 * bv.y; acc[3][2] += a3 * bv.z; acc[3][3] += a3 * bv.w;
        }
        __syncthreads();
    }
    float* outp = g_part + ((size_t)s * N_BOX) * H_DIM;
    #pragma unroll
    for (int i = 0; i < 4; i++) {
        int gr = row0 + ty * 4 + i;
        #pragma unroll
        for (int j = 0; j < 4; j++) {
            int gn = col0 + tx * 4 + j;
            outp[(size_t)gr * H_DIM + gn] = acc[i][j];
        }
    }
}

// ---------------- reduce partials + bias -> g_h1 ----------------
__global__ __launch_bounds__(512) void reduce_h1_kernel(const float* __restrict__ b_lin)
{
    int r = blockIdx.x, c = threadIdx.x;
    size_t o = (size_t)r * H_DIM + c;
    float v = b_lin[c];
    #pragma unroll
    for (int s = 0; s < NSPLIT; s++) v += g_part[(size_t)s * N_BOX * H_DIM + o];
    g_h1[o] = v;
}

// ---------------- generic fp32 SGEMM (dists): BM=16,BN=128,BK=16,128 thr ----------------
__global__ __launch_bounds__(128) void sgemm_kernel(
    const float* __restrict__ A, int lda,
    const float* __restrict__ B, int ldb,
    float* __restrict__ C, int ldc,
    int M, int N, int K,
    const float* __restrict__ bias)
{
    __shared__ float As[16][17];
    __shared__ float Bs[16][128];
    int tid = threadIdx.x;
    int tx = tid & 31, ty = tid >> 5;
    int row0 = blockIdx.y * 16;
    int col0 = blockIdx.x * 128;
    float acc[4][4];
    #pragma unroll
    for (int i = 0; i < 4; i++)
        #pragma unroll
        for (int j = 0; j < 4; j++) acc[i][j] = 0.f;

    for (int k0 = 0; k0 < K; k0 += 16) {
        #pragma unroll
        for (int i = 0; i < 2; i++) {
            int l = tid * 2 + i;
            int m = l >> 4, k = l & 15;
            int gr = row0 + m, gk = k0 + k;
            As[k][m] = (gr < M && gk < K) ? A[(size_t)gr * lda + gk] : 0.f;
        }
        #pragma unroll
        for (int i = 0; i < 4; i++) {
            int f = tid + i * 128;
            int k = f >> 5, n = (f & 31) << 2;
            int gk = k0 + k, gn = col0 + n;
            float4 v = make_float4(0.f, 0.f, 0.f, 0.f);
            if (gk < K) {
                float t0 = (gn + 0 < N) ? B[(size_t)gk * ldb + gn + 0] : 0.f;
                float t1 = (gn + 1 < N) ? B[(size_t)gk * ldb + gn + 1] : 0.f;
                float t2 = (gn + 2 < N) ? B[(size_t)gk * ldb + gn + 2] : 0.f;
                float t3 = (gn + 3 < N) ? B[(size_t)gk * ldb + gn + 3] : 0.f;
                v = make_float4(t0, t1, t2, t3);
            }
            *(float4*)&Bs[k][n] = v;
        }
        __syncthreads();
        #pragma unroll
        for (int k = 0; k < 16; k++) {
            float a0 = As[k][ty * 4 + 0];
            float a1 = As[k][ty * 4 + 1];
            float a2 = As[k][ty * 4 + 2];
            float a3 = As[k][ty * 4 + 3];
            float4 bv = *(float4*)&Bs[k][tx * 4];
            acc[0][0] += a0 * bv.x; acc[0][1] += a0 * bv.y; acc[0][2] += a0 * bv.z; acc[0][3] += a0 * bv.w;
            acc[1][0] += a1 * bv.x; acc[1][1] += a1 * bv.y; acc[1][2] += a1 * bv.z; acc[1][3] += a1 * bv.w;
            acc[2][0] += a2 * bv.x; acc[2][1] += a2 * bv.y; acc[2][2] += a2 * bv.z; acc[2][3] += a2 * bv.w;
            acc[3][0] += a3 * bv.x; acc[3][1] += a3 * bv.y; acc[3][2] += a3 * bv.z; acc[3][3] += a3 * bv.w;
        }
        __syncthreads();
    }
    #pragma unroll
    for (int i = 0; i < 4; i++) {
        int gr = row0 + ty * 4 + i;
        if (gr >= M) continue;
        #pragma unroll
        for (int j = 0; j < 4; j++) {
            int gn = col0 + tx * 4 + j;
            if (gn >= N) continue;
            C[(size_t)gr * ldc + gn] = acc[i][j] + bias[gn];
        }
    }
}

// ---------------- row softmax of obj_dists -> g_scores (col 0 = -1) ----------------
__global__ __launch_bounds__(256) void scores_kernel(const float* __restrict__ obj_dists)
{
    int row = blockIdx.x, tid = threadIdx.x;
    __shared__ float sred[8];
    float lv = (tid < C_CLS) ? obj_dists[row * C_CLS + tid] : FNEG_INF;
    float m = warp_max(lv);
    if ((tid & 31) == 0) sred[tid >> 5] = m;
    __syncthreads();
    float bm = sred[0];
    #pragma unroll
    for (int i = 1; i < 8; i++) bm = fmaxf(bm, sred[i]);
    float e = (tid < C_CLS) ? expf(lv - bm) : 0.f;
    float s = warp_sum(e);
    __syncthreads();
    if ((tid & 31) == 0) sred[tid >> 5] = s;
    __syncthreads();
    float bs = 0.f;
    #pragma unroll
    for (int i = 0; i < 8; i++) bs += sred[i];
    if (tid < C_CLS) g_scores[row * C_CLS + tid] = (tid == 0) ? -1.f : e / bs;
}

// ============== fused kernel: block0 = greedy NMS, other blocks = fcb/tab GEMMs ==============
#define FCB_MT 13                 /* ceil(400/32) */
#define FCB_BLOCKS (FCB_MT * 8)   /* 104 */
#define TAB_MT 5                  /* ceil(151/32) */
#define TAB_BLOCKS (TAB_MT * 8)   /* 40 */
#define FUSED_GRID (1 + FCB_BLOCKS + TAB_BLOCKS)

struct FusedSmem {
    float rowmax[N_BOX];
    int   rowarg[N_BOX];
    int   dirty [N_BOX];
    int   box, cls;
    float As[16 * 33];
    float Bs[16 * 64];
};

// 32x64 GEMM tile, 512 threads, 2x2 per thread
__device__ __forceinline__ void gemm_tile_32x64(
    const float* __restrict__ A0, int mode, int lda,   // mode 0: [x|pos] composite; mode 1: plain
    const float* __restrict__ x,
    const float* __restrict__ B,                       // ldb = 512
    float* __restrict__ Cg,
    int M, int K, const float* __restrict__ bias,
    int mt, int nt, float* As, float* Bs)
{
    int tid = threadIdx.x;
    int row0 = mt * 32, col0 = nt * 64;
    int tx = tid & 31, ty = tid >> 5;
    float acc00 = 0.f, acc01 = 0.f, acc10 = 0.f, acc11 = 0.f;

    for (int k0 = 0; k0 < K; k0 += 16) {
        {
            int m = tid & 31, k = tid >> 5;
            int gr = row0 + m, gk = k0 + k;
            float v = 0.f;
            if (gr < M && gk < K) {
                if (mode == 0)
                    v = (gk < D_X) ? x[(size_t)gr * D_X + gk]
                                   : g_tail[gr * TAIL_W + E_EMB + (gk - D_X)];
                else
                    v = A0[(size_t)gr * lda + gk];
            }
            As[k * 33 + m] = v;
        }
        {
            int k = tid >> 5, n = (tid & 31) * 2;
            int gk = k0 + k;
            float2 v = make_float2(0.f, 0.f);
            if (gk < K) v = *(const float2*)(B + (size_t)gk * H_DIM + col0 + n);
            *(float2*)(Bs + k * 64 + n) = v;
        }
        __syncthreads();
        #pragma unroll
        for (int k = 0; k < 16; k++) {
            float a0 = As[k * 33 + ty * 2 + 0];
            float a1 = As[k * 33 + ty * 2 + 1];
            float2 b = *(float2*)(Bs + k * 64 + tx * 2);
            acc00 += a0 * b.x; acc01 += a0 * b.y;
            acc10 += a1 * b.x; acc11 += a1 * b.y;
        }
        __syncthreads();
    }
    int gr0 = row0 + ty * 2, gn = col0 + tx * 2;
    float bx = bias ? bias[gn] : 0.f;
    float by = bias ? bias[gn + 1] : 0.f;
    if (gr0 < M)     { Cg[(size_t)gr0 * H_DIM + gn] = acc00 + bx; Cg[(size_t)gr0 * H_DIM + gn + 1] = acc01 + by; }
    if (gr0 + 1 < M) { Cg[(size_t)(gr0 + 1) * H_DIM + gn] = acc10 + bx; Cg[(size_t)(gr0 + 1) * H_DIM + gn + 1] = acc11 + by; }
}

__global__ __launch_bounds__(512, 1) void fused_kernel(
    const float* __restrict__ x,
    const float* __restrict__ w_fc, const float* __restrict__ b_fc,
    const float* __restrict__ objw2)
{
    __shared__ FusedSmem sm;
    int bid = blockIdx.x;
    int tid = threadIdx.x;

    if (bid >= 1 && bid < 1 + FCB_BLOCKS) {
        int bi = bid - 1;
        gemm_tile_32x64(0, 0, 0, x, w_fc, g_fcb, N_BOX, K_REP2, b_fc,
                        bi >> 3, bi & 7, sm.As, sm.Bs);
        return;
    }
    if (bid >= 1 + FCB_BLOCKS) {
        int bj = bid - 1 - FCB_BLOCKS;
        gemm_tile_32x64(objw2, 1, E_EMB, x, w_fc + (size_t)K_REP2 * H_DIM, g_tab,
                        C_CLS, E_EMB, 0, bj >> 3, bj & 7, sm.As, sm.Bs);
        return;
    }

    // ---------------- block 0: greedy NMS ----------------
    int wid = tid >> 5, lane = tid & 31;

    // init: each warp scans rows (exact max + first argmax)
    for (int r = wid; r < N_BOX; r += 16) {
        float best = -2.f; int bi2 = 0x7fffffff;
        const float* sr = g_scores + r * C_CLS;
        for (int c = lane; c < C_CLS; c += 32) {
            float vv = sr[c];
            if (vv > best) { best = vv; bi2 = c; }
        }
        #pragma unroll
        for (int o = 16; o; o >>= 1) {
            float ov = __shfl_xor_sync(0xffffffffu, best, o);
            int   oi = __shfl_xor_sync(0xffffffffu, bi2, o);
            if (ov > best || (ov == best && oi < bi2)) { best = ov; bi2 = oi; }
        }
        if (lane == 0) { sm.rowmax[r] = best; sm.rowarg[r] = bi2; sm.dirty[r] = 0; }
    }
    if (tid < N_BOX) g_labels[tid] = 0;
    __syncthreads();

    for (int it = 0; it < N_BOX; it++) {
        // ---- warp 0: lazy argmax with on-demand rescans ----
        if (wid == 0) {
            int rsel;
            for (;;) {
                float best = FNEG_INF; int bi2 = 0x7fffffff;
                for (int r = lane; r < N_BOX; r += 32) {
                    float vv = sm.rowmax[r];
                    if (vv > best) { best = vv; bi2 = r; }
                }
                #pragma unroll
                for (int o = 16; o; o >>= 1) {
                    float ov = __shfl_xor_sync(0xffffffffu, best, o);
                    int   oi = __shfl_xor_sync(0xffffffffu, bi2, o);
                    if (ov > best || (ov == best && oi < bi2)) { best = ov; bi2 = oi; }
                }
                rsel = bi2;
                if (!sm.dirty[rsel]) break;
                // rescan row rsel
                float m2 = -2.f; int a2 = 0x7fffffff;
                const float* sr = g_scores + rsel * C_CLS;
                for (int c = lane; c < C_CLS; c += 32) {
                    float vv = sr[c];
                    if (vv > m2) { m2 = vv; a2 = c; }
                }
                #pragma unroll
                for (int o = 16; o; o >>= 1) {
                    float ov = __shfl_xor_sync(0xffffffffu, m2, o);
                    int   oi = __shfl_xor_sync(0xffffffffu, a2, o);
                    if (ov > m2 || (ov == m2 && oi < a2)) { m2 = ov; a2 = oi; }
                }
                if (lane == 0) { sm.rowmax[rsel] = m2; sm.rowarg[rsel] = a2; sm.dirty[rsel] = 0; }
                __syncwarp();
            }
            if (lane == 0) {
                int cls = sm.rowarg[rsel];
                sm.box = rsel; sm.cls = cls;
                g_labels[rsel] = cls;
            }
        }
        __syncthreads();   // (1) selection broadcast

        int box = sm.box, cls = sm.cls;
        if (tid < N_BOX) {
            int r = tid;
            if (r == box) {
                sm.rowmax[r] = -1.f; sm.rowarg[r] = 0; sm.dirty[r] = 0;
            } else {
                const float4* bt = (const float4*)g_boxT + (size_t)cls * N_BOX;
                float4 sb = bt[box];
                float4 bb = bt[r];
                float x1 = fmaxf(bb.x, sb.x);
                float y1 = fmaxf(bb.y, sb.y);
                float x2 = fminf(bb.z, sb.z);
                float y2 = fminf(bb.w, sb.w);
                float inter = fmaxf(x2 - x1 + 1.f, 0.f) * fmaxf(y2 - y1 + 1.f, 0.f);
                float area  = (bb.z - bb.x + 1.f) * (bb.w - bb.y + 1.f);
                float sarea = (sb.z - sb.x + 1.f) * (sb.w - sb.y + 1.f);
                float uni = area + sarea - inter;
                if (inter / uni >= 0.5f) {
                    g_scores[r * C_CLS + cls] = 0.f;
                    if (!sm.dirty[r]) {
                        int   ac = sm.rowarg[r];
                        float mx = sm.rowmax[r];
                        if (ac == cls) sm.dirty[r] = 1;
                        else if (0.f > mx) { sm.rowmax[r] = 0.f; sm.rowarg[r] = cls; }
                        else if (0.f == mx && cls < ac) sm.rowarg[r] = cls;
                    }
                }
            }
        } else {
            int c = tid - N_BOX;
            if (c < C_CLS) g_scores[box * C_CLS + c] = -1.f;
            c += 112;
            if (c < C_CLS) g_scores[box * C_CLS + c] = -1.f;
        }
        __syncthreads();   // (2) masking complete
    }
}

// ---------------- final: edge_ctx = relu(fcb + tab[label]); preds as float ----------------
__global__ __launch_bounds__(128) void edge_kernel(float* __restrict__ out)
{
    int row = blockIdx.x, tid = threadIdx.x;
    int lab = g_labels[row];
    if (tid == 0) out[N_BOX * C_CLS + row] = (float)lab;
    const float* fb = g_fcb + (size_t)row * H_DIM;
    const float* tb = g_tab + (size_t)lab * H_DIM;
    float* o = out + N_BOX * C_CLS + N_BOX + (size_t)row * H_DIM;
    for (int c = tid; c < H_DIM; c += 128) o[c] = fmaxf(fb[c] + tb[c], 0.f);
}

// ---------------- launch ----------------
extern "C" void kernel_launch(void* const* d_in, const int* in_sizes, int n_in,
                              void* d_out, int out_size)
{
    const float* x        = (const float*)d_in[0];
    const float* logits   = (const float*)d_in[1];
    const float* pos      = (const float*)d_in[2];
    const float* boxes    = (const float*)d_in[3];
    const float* objw     = (const float*)d_in[4];
    const float* objw2    = (const float*)d_in[5];
    const float* w_pos1   = (const float*)d_in[6];
    const float* b_pos1   = (const float*)d_in[7];
    const float* bn_g     = (const float*)d_in[8];
    const float* bn_b     = (const float*)d_in[9];
    const float* bn_m     = (const float*)d_in[10];
    const float* bn_v     = (const float*)d_in[11];
    const float* w_pos2   = (const float*)d_in[12];
    const float* b_pos2   = (const float*)d_in[13];
    const float* w_lin    = (const float*)d_in[14];
    const float* b_lin    = (const float*)d_in[15];
    const float* w_out    = (const float*)d_in[16];
    const float* b_out    = (const float*)d_in[17];
    const float* w_fc     = (const float*)d_in[18];
    const float* b_fc     = (const float*)d_in[19];
    float* out = (float*)d_out;

    float *h1;
    cudaGetSymbolAddress((void**)&h1, g_h1);

    // 1) boxes transpose (for coalesced greedy reads)
    transpose_boxes<<<N_BOX, 160>>>(boxes);
    // 2) feature prep -> g_tail
    prep_kernel<<<N_BOX, 256>>>(logits, pos, objw, w_pos1, b_pos1,
                                bn_g, bn_b, bn_m, bn_v, w_pos2, b_pos2);
    // 3) h1 split-K GEMM (full-chip)
    h1_splitk_kernel<<<dim3(4, 25, NSPLIT), 128>>>(x, w_lin);
    // 4) reduce partials + bias
    reduce_h1_kernel<<<N_BOX, 512>>>(b_lin);
    // 5) obj_dists = h1 @ w_out + b_out  -> out[0 : 400*151]
    sgemm_kernel<<<dim3(2, 25), 128>>>(h1, H_DIM, w_out, C_CLS, out, C_CLS,
                                       N_BOX, C_CLS, H_DIM, b_out);
    // 6) scores = softmax(obj_dists), col0 = -1
    scores_kernel<<<N_BOX, 256>>>(out);
    // 7) fused: greedy NMS (block 0) || fcb GEMM || tab GEMM
    fused_kernel<<<FUSED_GRID, 512>>>(x, w_fc, b_fc, objw2);
    // 8) edge_ctx = relu(fcb + tab[label]); preds as float
    edge_kernel<<<N_BOX, 128>>>(out);
}